// round 15
// baseline (speedup 1.0000x reference)
#include <cuda_runtime.h>
#include <cuda_bf16.h>
#include <cuda_fp16.h>
#include <math.h>
#include <stdint.h>

// Problem constants
#define BB 4
#define BN 512
#define BH 32
#define NROWS 2048

// ---------------- scratch (static device globals; no allocs) ----------------
__device__ float g_Q [NROWS*64];
__device__ float g_K [NROWS*64];   // pre-scaled by DH^-0.5
__device__ float g_VT[BB*64*BN];   // V transposed: [b][c][j]
__device__ float g_Q2[NROWS*64];
__device__ float g_K2[NROWS*64];   // pre-scaled
__device__ float g_WET [64*64];    // W_E^T  : [hk][d]
__device__ float g_WE2T[64*64];    // W_E2^T : [hk][d]
__device__ __half g_scores[(size_t)BH*BN*BN];
__device__ float g_hatt[NROWS*64];

// ---------------- helpers ----------------
__device__ __forceinline__ void mma_e4m3(float c[4],
    uint32_t a0, uint32_t a1, uint32_t a2, uint32_t a3,
    uint32_t b0, uint32_t b1)
{
    asm volatile(
        "mma.sync.aligned.m16n8k32.row.col.f32.e4m3.e4m3.f32 "
        "{%0,%1,%2,%3}, {%4,%5,%6,%7}, {%8,%9}, {%0,%1,%2,%3};"
        : "+f"(c[0]), "+f"(c[1]), "+f"(c[2]), "+f"(c[3])
        : "r"(a0), "r"(a1), "r"(a2), "r"(a3), "r"(b0), "r"(b1));
}
// pack 4 floats -> 4 e4m3 bytes (x0 = lowest byte)
__device__ __forceinline__ uint32_t packe4(float x0, float x1, float x2, float x3) {
    uint16_t lo, hi;
    asm("cvt.rn.satfinite.e4m3x2.f32 %0, %1, %2;" : "=h"(lo) : "f"(x1), "f"(x0));
    asm("cvt.rn.satfinite.e4m3x2.f32 %0, %1, %2;" : "=h"(hi) : "f"(x3), "f"(x2));
    return (uint32_t)lo | ((uint32_t)hi << 16);
}

#define SME8 80   // e4m3 smem row stride in bytes (conflict-free frag loads)

// ---------------- K0: transpose W_E, W_E2 ----------------
__global__ void __launch_bounds__(256) k0_init(const float* __restrict__ WE,
                                               const float* __restrict__ WE2) {
    int t = threadIdx.x;
    for (int i = t; i < 4096; i += 256) {
        int d = i >> 6, c = i & 63;
        g_WET [c*64 + d] = WE [i];
        g_WE2T[c*64 + d] = WE2[i];
    }
}

// ---------------- K1: x = LN(h+p); projections. 4 rows/block ----------------
__global__ void __launch_bounds__(256) k1_proj(
    const float* __restrict__ h, const float* __restrict__ p,
    const float* __restrict__ g1, const float* __restrict__ b1,
    const float* __restrict__ WQ, const float* __restrict__ WK,
    const float* __restrict__ WV, const float* __restrict__ WQ2,
    const float* __restrict__ WK2)
{
    int ty = threadIdx.y;
    int row = blockIdx.x*4 + ty;
    int b = row >> 9, n = row & 511;
    int t = threadIdx.x;
    __shared__ float xs[4][64];
    __shared__ float red[4][4];

    float v = h[row*64 + t] + p[row*64 + t];
    float s = v, sq = v*v;
    #pragma unroll
    for (int off = 16; off; off >>= 1) {
        s  += __shfl_down_sync(0xffffffffu, s,  off);
        sq += __shfl_down_sync(0xffffffffu, sq, off);
    }
    int wid = t >> 5, lane = t & 31;
    if (lane == 0) { red[ty][wid*2] = s; red[ty][wid*2+1] = sq; }
    __syncthreads();
    float S  = red[ty][0] + red[ty][2];
    float SQ = red[ty][1] + red[ty][3];
    float mean = S * (1.f/64.f);
    float var  = SQ * (1.f/64.f) - mean*mean;
    float rinv = rsqrtf(var + 1e-5f);
    xs[ty][t] = (v - mean) * rinv * g1[t] + b1[t];
    __syncthreads();

    float q = 0.f, k = 0.f, vv = 0.f, q2 = 0.f, k2 = 0.f;
    #pragma unroll 8
    for (int d = 0; d < 64; ++d) {
        float x = xs[ty][d];
        q  += x * WQ [d*64 + t];
        k  += x * WK [d*64 + t];
        vv += x * WV [d*64 + t];
        q2 += x * WQ2[d*64 + t];
        k2 += x * WK2[d*64 + t];
    }
    const float sc = 0.35355339059327373f;  // 8^-0.5
    g_Q [row*64 + t] = q;
    g_K [row*64 + t] = k * sc;
    g_VT[((size_t)b*64 + t)*512 + n] = vv;
    g_Q2[row*64 + t] = q2;
    g_K2[row*64 + t] = k2 * sc;
}

// ---------------- K2: BOTH edge paths dense via fp8, adj-select epilogue ----
// Block = one (b,i), 128 threads = 4 warps, 8 j-tiles of 64.
// Y2 = e @ (W_E2 o Q2)^T and Y1 = e @ (W_E o Q)^T, both e4m3 (x16 prescale).
// score[h,j] = (adj ? <Y1,K> : <Y2,K2>) / 16. One kernel, no sparse pass.
#define K2_SMEM (3*64*SME8)    // 15360 B
__global__ void __launch_bounds__(128) k2_dense(
    const float* __restrict__ e, const unsigned* __restrict__ adj)
{
    extern __shared__ char dyn[];
    uint8_t* es  = (uint8_t*)dyn;                 // [64][SME8] row=j, col=d
    uint8_t* A2s = (uint8_t*)(dyn + 64*SME8);     // [64][SME8] row=hk
    uint8_t* A1s = (uint8_t*)(dyn + 2*64*SME8);
    __shared__ float q2s[64], qs[64];
    __shared__ unsigned char adjf[64];

    int bi = blockIdx.x;
    int b = bi >> 9, i = bi & 511;
    int t = threadIdx.x;
    int lane = t & 31;
    int r = lane >> 2, cq = lane & 3;
    int m0 = (t >> 5) * 16;

    if (t < 64) q2s[t] = g_Q2[bi*64 + t];
    else        qs[t-64] = g_Q[bi*64 + t - 64];
    __syncthreads();
    // A2s/A1s[hk][d] = e4m3(W^T[hk][d] * q[hk] * 16)
    #pragma unroll
    for (int it = 0; it < 8; ++it) {
        int idx = t + it*128;                 // u32 group: 1024 total
        int hk = idx >> 4, c4 = idx & 15;
        float4 w2 = ((const float4*)g_WE2T)[hk*16 + c4];
        float4 w1 = ((const float4*)g_WET )[hk*16 + c4];
        float q2v = q2s[hk] * 16.f;
        float q1v = qs[hk]  * 16.f;
        *(uint32_t*)&A2s[hk*SME8 + c4*4] = packe4(w2.x*q2v, w2.y*q2v, w2.z*q2v, w2.w*q2v);
        *(uint32_t*)&A1s[hk*SME8 + c4*4] = packe4(w1.x*q1v, w1.y*q1v, w1.z*q1v, w1.w*q1v);
    }

    const float4* ebase = (const float4*)(e + (size_t)bi * BN * 64);
    const unsigned* abase = adj + (size_t)bi * BN;
    int jl0 = m0 + r, jl1 = jl0 + 8;

    for (int jt = 0; jt < 8; ++jt) {
        int j0 = jt * 64;
        __syncthreads();      // es/adjf free (covers A build on first iter)
        #pragma unroll
        for (int it = 0; it < 8; ++it) {
            int idx = t + it*128;
            int jl = idx >> 4, c4 = idx & 15;
            float4 v = ebase[(size_t)(j0 + jl)*16 + c4];
            *(uint32_t*)&es[jl*SME8 + c4*4] = packe4(v.x, v.y, v.z, v.w);
        }
        if (t < 64) adjf[t] = abase[j0 + t] ? 1 : 0;
        __syncthreads();

        float acc2[8][4], acc1[8][4];
        #pragma unroll
        for (int nt = 0; nt < 8; ++nt)
            #pragma unroll
            for (int z = 0; z < 4; ++z) { acc2[nt][z] = 0.f; acc1[nt][z] = 0.f; }

        // K=64 via 2 x k32 fp8 mma, 8 n-tiles, two B operands
        #pragma unroll
        for (int kc = 0; kc < 2; ++kc) {
            int k0 = kc*32 + cq*4;
            uint32_t a0 = *(const uint32_t*)&es[jl0*SME8 + k0];
            uint32_t a1 = *(const uint32_t*)&es[jl1*SME8 + k0];
            uint32_t a2 = *(const uint32_t*)&es[jl0*SME8 + k0 + 16];
            uint32_t a3 = *(const uint32_t*)&es[jl1*SME8 + k0 + 16];
            #pragma unroll
            for (int nt = 0; nt < 8; ++nt) {
                int n = nt*8 + r;
                uint32_t b20 = *(const uint32_t*)&A2s[n*SME8 + k0];
                uint32_t b21 = *(const uint32_t*)&A2s[n*SME8 + k0 + 16];
                mma_e4m3(acc2[nt], a0, a1, a2, a3, b20, b21);
                uint32_t b10 = *(const uint32_t*)&A1s[n*SME8 + k0];
                uint32_t b11 = *(const uint32_t*)&A1s[n*SME8 + k0 + 16];
                mma_e4m3(acc1[nt], a0, a1, a2, a3, b10, b11);
            }
        }

        // epilogue: select path per row BEFORE quad-reduce (adj uniform in quad)
        bool a0f = adjf[jl0] != 0, a1f = adjf[jl1] != 0;
        const float* k2r0 = g_K2 + ((size_t)(b*512 + j0 + jl0))*64 + 2*cq;
        const float* k2r1 = g_K2 + ((size_t)(b*512 + j0 + jl1))*64 + 2*cq;
        const float* k1r0 = g_K  + ((size_t)(b*512 + j0 + jl0))*64 + 2*cq;
        const float* k1r1 = g_K  + ((size_t)(b*512 + j0 + jl1))*64 + 2*cq;
        #pragma unroll
        for (int h = 0; h < 8; ++h) {
            float2 ca0 = __ldg((const float2*)((a0f ? k1r0 : k2r0) + h*8));
            float2 ca1 = __ldg((const float2*)((a1f ? k1r1 : k2r1) + h*8));
            float p00 = a0f ? acc1[h][0] : acc2[h][0];
            float p01 = a0f ? acc1[h][1] : acc2[h][1];
            float p10 = a1f ? acc1[h][2] : acc2[h][2];
            float p11 = a1f ? acc1[h][3] : acc2[h][3];
            float s0 = (p00*ca0.x + p01*ca0.y) * 0.0625f;
            float s1 = (p10*ca1.x + p11*ca1.y) * 0.0625f;
            s0 += __shfl_xor_sync(0xffffffffu, s0, 1);
            s0 += __shfl_xor_sync(0xffffffffu, s0, 2);
            s1 += __shfl_xor_sync(0xffffffffu, s1, 1);
            s1 += __shfl_xor_sync(0xffffffffu, s1, 2);
            if (cq == 0) {
                size_t srow = ((size_t)(b*8 + h)*BN + i)*BN + j0;
                g_scores[srow + jl0] = __float2half(s0);
                g_scores[srow + jl1] = __float2half(s1);
            }
        }
    }
}

// ---------------- K4: exp/mask/k_RW + rowsum + att@V (half scores) -----------
__global__ void __launch_bounds__(256) k4_att(
    const float* __restrict__ kRW, const float* __restrict__ mask)
{
    __shared__ float Vs[8*512];   // 16 KB
    __shared__ float msk[512];
    int bh = blockIdx.y;
    int b = bh >> 3, h = bh & 7;
    int i0 = blockIdx.x * 8;
    int t = threadIdx.x, w = t >> 5, lane = t & 31;

    const float4* vtp = (const float4*)(g_VT + ((size_t)(b*64) + h*8)*512);
    #pragma unroll
    for (int idx = t; idx < 1024; idx += 256)
        ((float4*)Vs)[idx] = vtp[idx];
    for (int j = t; j < 512; j += 256) msk[j] = mask[b*512 + j];
    __syncthreads();

    int i = i0 + w;
    float mi = msk[i];
    const __half* sp = g_scores + ((size_t)(b*8 + h)*512 + i)*512;
    const float* wp = kRW + ((size_t)(b*512 + i))*512;

    float pden = 0.f;
    float pav[8];
    #pragma unroll
    for (int k = 0; k < 8; ++k) pav[k] = 0.f;

    #pragma unroll 4
    for (int jt = 0; jt < 16; ++jt) {
        int j = jt*32 + lane;
        float pw = __expf(__half2float(sp[j])) * wp[j] * msk[j] * mi;
        pden += pw;
        #pragma unroll
        for (int k = 0; k < 8; ++k) pav[k] += pw * Vs[k*512 + j];
    }
    #pragma unroll
    for (int off = 16; off; off >>= 1) {
        pden += __shfl_down_sync(0xffffffffu, pden, off);
        #pragma unroll
        for (int k = 0; k < 8; ++k) pav[k] += __shfl_down_sync(0xffffffffu, pav[k], off);
    }
    if (lane == 0) {
        float inv = 1.f / fmaxf(pden, 1e-6f);
        float4* op = (float4*)&g_hatt[((size_t)(b*512 + i))*64 + h*8];
        op[0] = make_float4(pav[0]*inv, pav[1]*inv, pav[2]*inv, pav[3]*inv);
        op[1] = make_float4(pav[4]*inv, pav[5]*inv, pav[6]*inv, pav[7]*inv);
    }
}

// ---------------- K5: O-proj + LN2 + FFN + residuals. 4 rows/block ----------
__global__ void __launch_bounds__(256) k5_out(
    const float* __restrict__ hin, const float* __restrict__ OW,
    const float* __restrict__ Ob, const float* __restrict__ g2,
    const float* __restrict__ b2, const float* __restrict__ Wf1,
    const float* __restrict__ bf1, const float* __restrict__ Wf2,
    const float* __restrict__ bf2, float* __restrict__ out)
{
    int ty = threadIdx.y;
    int row = blockIdx.x*4 + ty;
    int t = threadIdx.x;
    __shared__ float has[4][64], ys[4][64], hid[4][128];
    __shared__ float red[4][4];

    has[ty][t] = g_hatt[row*64 + t];
    __syncthreads();

    float a = hin[row*64 + t] + Ob[t];
    #pragma unroll 8
    for (int d = 0; d < 64; ++d) a += has[ty][d] * OW[d*64 + t];

    float s = a, sq = a*a;
    #pragma unroll
    for (int off = 16; off; off >>= 1) {
        s  += __shfl_down_sync(0xffffffffu, s,  off);
        sq += __shfl_down_sync(0xffffffffu, sq, off);
    }
    int wid = t >> 5, lane = t & 31;
    if (lane == 0) { red[ty][wid*2] = s; red[ty][wid*2+1] = sq; }
    __syncthreads();
    float S  = red[ty][0] + red[ty][2];
    float SQ = red[ty][1] + red[ty][3];
    float mean = S * (1.f/64.f);
    float var  = SQ * (1.f/64.f) - mean*mean;
    float rinv = rsqrtf(var + 1e-5f);
    ys[ty][t] = (a - mean) * rinv * g2[t] + b2[t];
    __syncthreads();

    float h0 = bf1[t], h1 = bf1[t + 64];
    #pragma unroll 8
    for (int d = 0; d < 64; ++d) {
        float x = ys[ty][d];
        h0 += x * Wf1[d*128 + t];
        h1 += x * Wf1[d*128 + t + 64];
    }
    hid[ty][t]      = fmaxf(h0, 0.f);
    hid[ty][t + 64] = fmaxf(h1, 0.f);
    __syncthreads();

    float o = a + bf2[t];
    #pragma unroll 8
    for (int c = 0; c < 128; ++c) o += hid[ty][c] * Wf2[c*64 + t];
    out[row*64 + t] = o;
}

// ---------------- launch ----------------
extern "C" void kernel_launch(void* const* d_in, const int* in_sizes, int n_in,
                              void* d_out, int out_size)
{
    const float* h    = (const float*)d_in[0];
    const float* p    = (const float*)d_in[1];
    const float* e    = (const float*)d_in[2];
    const float* kRW  = (const float*)d_in[3];
    const float* mask = (const float*)d_in[4];
    const unsigned* adj = (const unsigned*)d_in[5];
    const float* WQ   = (const float*)d_in[6];
    const float* WK   = (const float*)d_in[7];
    const float* WV   = (const float*)d_in[8];
    const float* WQ2  = (const float*)d_in[9];
    const float* WK2  = (const float*)d_in[10];
    const float* WE   = (const float*)d_in[11];
    const float* WE2  = (const float*)d_in[12];
    const float* OW   = (const float*)d_in[13];
    const float* Ob   = (const float*)d_in[14];
    const float* g1   = (const float*)d_in[15];
    const float* b1   = (const float*)d_in[16];
    const float* g2   = (const float*)d_in[17];
    const float* b2   = (const float*)d_in[18];
    const float* Wf1  = (const float*)d_in[19];
    const float* bf1  = (const float*)d_in[20];
    const float* Wf2  = (const float*)d_in[21];
    const float* bf2  = (const float*)d_in[22];
    float* out = (float*)d_out;

    k0_init<<<1, 256>>>(WE, WE2);
    k1_proj<<<512, dim3(64,4)>>>(h, p, g1, b1, WQ, WK, WV, WQ2, WK2);
    k2_dense<<<NROWS, 128, K2_SMEM>>>(e, adj);
    k4_att<<<dim3(64, 32), 256>>>(kRW, mask);
    k5_out<<<512, dim3(64,4)>>>(h, OW, Ob, g2, b2, Wf1, bf1, Wf2, bf2, out);
}

// round 16
// speedup vs baseline: 1.1231x; 1.1231x over previous
#include <cuda_runtime.h>
#include <cuda_bf16.h>
#include <cuda_fp16.h>
#include <math.h>
#include <stdint.h>

// Problem constants
#define BB 4
#define BN 512
#define BH 32
#define NROWS 2048

// ---------------- scratch (static device globals; no allocs) ----------------
__device__ float g_Q [NROWS*64];
__device__ float g_K [NROWS*64];   // pre-scaled by DH^-0.5
__device__ float g_VT[BB*64*BN];   // V transposed: [b][c][j]
__device__ float g_Q2[NROWS*64];
__device__ float g_K2[NROWS*64];   // pre-scaled
__device__ float g_WET [64*64];    // W_E^T  : [hk][d]
__device__ float g_WE2T[64*64];    // W_E2^T : [hk][d]
__device__ __half g_scores[(size_t)BH*BN*BN];
__device__ float g_hatt[NROWS*64];

// ---------------- helpers ----------------
__device__ __forceinline__ void mma_e4m3(float c[4],
    uint32_t a0, uint32_t a1, uint32_t a2, uint32_t a3,
    uint32_t b0, uint32_t b1)
{
    asm volatile(
        "mma.sync.aligned.m16n8k32.row.col.f32.e4m3.e4m3.f32 "
        "{%0,%1,%2,%3}, {%4,%5,%6,%7}, {%8,%9}, {%0,%1,%2,%3};"
        : "+f"(c[0]), "+f"(c[1]), "+f"(c[2]), "+f"(c[3])
        : "r"(a0), "r"(a1), "r"(a2), "r"(a3), "r"(b0), "r"(b1));
}
// pack 4 floats -> 4 e4m3 bytes (x0 = lowest byte)
__device__ __forceinline__ uint32_t packe4(float x0, float x1, float x2, float x3) {
    uint16_t lo, hi;
    asm("cvt.rn.satfinite.e4m3x2.f32 %0, %1, %2;" : "=h"(lo) : "f"(x1), "f"(x0));
    asm("cvt.rn.satfinite.e4m3x2.f32 %0, %1, %2;" : "=h"(hi) : "f"(x3), "f"(x2));
    return (uint32_t)lo | ((uint32_t)hi << 16);
}

#define SME8 80   // e4m3 smem row stride in bytes (conflict-free frag loads)

// ---------------- K0: transpose W_E, W_E2 ----------------
__global__ void __launch_bounds__(256) k0_init(const float* __restrict__ WE,
                                               const float* __restrict__ WE2) {
    int t = threadIdx.x;
    for (int i = t; i < 4096; i += 256) {
        int d = i >> 6, c = i & 63;
        g_WET [c*64 + d] = WE [i];
        g_WE2T[c*64 + d] = WE2[i];
    }
}

// ---------------- K1: x = LN(h+p); projections. 4 rows/block ----------------
__global__ void __launch_bounds__(256) k1_proj(
    const float* __restrict__ h, const float* __restrict__ p,
    const float* __restrict__ g1, const float* __restrict__ b1,
    const float* __restrict__ WQ, const float* __restrict__ WK,
    const float* __restrict__ WV, const float* __restrict__ WQ2,
    const float* __restrict__ WK2)
{
    int ty = threadIdx.y;
    int row = blockIdx.x*4 + ty;
    int b = row >> 9, n = row & 511;
    int t = threadIdx.x;
    __shared__ float xs[4][64];
    __shared__ float red[4][4];

    float v = h[row*64 + t] + p[row*64 + t];
    float s = v, sq = v*v;
    #pragma unroll
    for (int off = 16; off; off >>= 1) {
        s  += __shfl_down_sync(0xffffffffu, s,  off);
        sq += __shfl_down_sync(0xffffffffu, sq, off);
    }
    int wid = t >> 5, lane = t & 31;
    if (lane == 0) { red[ty][wid*2] = s; red[ty][wid*2+1] = sq; }
    __syncthreads();
    float S  = red[ty][0] + red[ty][2];
    float SQ = red[ty][1] + red[ty][3];
    float mean = S * (1.f/64.f);
    float var  = SQ * (1.f/64.f) - mean*mean;
    float rinv = rsqrtf(var + 1e-5f);
    xs[ty][t] = (v - mean) * rinv * g1[t] + b1[t];
    __syncthreads();

    float q = 0.f, k = 0.f, vv = 0.f, q2 = 0.f, k2 = 0.f;
    #pragma unroll 8
    for (int d = 0; d < 64; ++d) {
        float x = xs[ty][d];
        q  += x * WQ [d*64 + t];
        k  += x * WK [d*64 + t];
        vv += x * WV [d*64 + t];
        q2 += x * WQ2[d*64 + t];
        k2 += x * WK2[d*64 + t];
    }
    const float sc = 0.35355339059327373f;  // 8^-0.5
    g_Q [row*64 + t] = q;
    g_K [row*64 + t] = k * sc;
    g_VT[((size_t)b*64 + t)*512 + n] = vv;
    g_Q2[row*64 + t] = q2;
    g_K2[row*64 + t] = k2 * sc;
}

// ---------------- K2a: dense E2 scores via fp8 e4m3 (round-14 proven) -------
#define K2_SMEM (2*64*SME8)
__global__ void __launch_bounds__(128) k2_dense(const float* __restrict__ e)
{
    extern __shared__ char dyn[];
    uint8_t* es  = (uint8_t*)dyn;               // [64][SME8] row=j, col=d
    uint8_t* A2s = (uint8_t*)(dyn + 64*SME8);   // [64][SME8] row=hk, col=d
    __shared__ float q2s[64];

    int bi = blockIdx.x;
    int b = bi >> 9, i = bi & 511;
    int t = threadIdx.x;
    int lane = t & 31;
    int r = lane >> 2, cq = lane & 3;
    int m0 = (t >> 5) * 16;

    if (t < 64) q2s[t] = g_Q2[bi*64 + t];
    __syncthreads();
    // A2s[hk][d] = e4m3(W_E2^T[hk][d] * q2[hk] * 16)
    #pragma unroll
    for (int it = 0; it < 8; ++it) {
        int idx = t + it*128;
        int hk = idx >> 4, c4 = idx & 15;
        float4 wv = ((const float4*)g_WE2T)[hk*16 + c4];
        float qv = q2s[hk] * 16.f;
        *(uint32_t*)&A2s[hk*SME8 + c4*4] =
            packe4(wv.x*qv, wv.y*qv, wv.z*qv, wv.w*qv);
    }

    const float4* ebase = (const float4*)(e + (size_t)bi * BN * 64);
    int jl0 = m0 + r, jl1 = jl0 + 8;

    for (int jt = 0; jt < 8; ++jt) {
        int j0 = jt * 64;
        __syncthreads();      // es free (covers A2s build on first iter)
        #pragma unroll
        for (int it = 0; it < 8; ++it) {
            int idx = t + it*128;
            int jl = idx >> 4, c4 = idx & 15;
            float4 v = ebase[(size_t)(j0 + jl)*16 + c4];
            *(uint32_t*)&es[jl*SME8 + c4*4] = packe4(v.x, v.y, v.z, v.w);
        }
        __syncthreads();

        // prefetch K2 fragments (L2-hot, hidden behind mma)
        const float* kr0 = g_K2 + ((size_t)(b*512 + j0 + jl0))*64 + 2*cq;
        const float* kr1 = g_K2 + ((size_t)(b*512 + j0 + jl1))*64 + 2*cq;
        float2 ka[8], kb[8];
        #pragma unroll
        for (int h = 0; h < 8; ++h) {
            ka[h] = __ldg((const float2*)(kr0 + h*8));
            kb[h] = __ldg((const float2*)(kr1 + h*8));
        }

        float acc[8][4];
        #pragma unroll
        for (int nt = 0; nt < 8; ++nt)
            #pragma unroll
            for (int z = 0; z < 4; ++z) acc[nt][z] = 0.f;

        // K=64 via 2 x k32 fp8 mma, 8 n-tiles
        #pragma unroll
        for (int kc = 0; kc < 2; ++kc) {
            int k0 = kc*32 + cq*4;
            uint32_t a0 = *(const uint32_t*)&es[jl0*SME8 + k0];
            uint32_t a1 = *(const uint32_t*)&es[jl1*SME8 + k0];
            uint32_t a2 = *(const uint32_t*)&es[jl0*SME8 + k0 + 16];
            uint32_t a3 = *(const uint32_t*)&es[jl1*SME8 + k0 + 16];
            #pragma unroll
            for (int nt = 0; nt < 8; ++nt) {
                int n = nt*8 + r;
                uint32_t b0 = *(const uint32_t*)&A2s[n*SME8 + k0];
                uint32_t b1 = *(const uint32_t*)&A2s[n*SME8 + k0 + 16];
                mma_e4m3(acc[nt], a0, a1, a2, a3, b0, b1);
            }
        }

        // epilogue: score[h,j] = <Y, K2>/16 (undo A2 x16)
        #pragma unroll
        for (int h = 0; h < 8; ++h) {
            float s0 = (acc[h][0]*ka[h].x + acc[h][1]*ka[h].y) * 0.0625f;
            float s1 = (acc[h][2]*kb[h].x + acc[h][3]*kb[h].y) * 0.0625f;
            s0 += __shfl_xor_sync(0xffffffffu, s0, 1);
            s0 += __shfl_xor_sync(0xffffffffu, s0, 2);
            s1 += __shfl_xor_sync(0xffffffffu, s1, 1);
            s1 += __shfl_xor_sync(0xffffffffu, s1, 2);
            if (cq == 0) {
                size_t srow = ((size_t)(b*8 + h)*BN + i)*BN + j0;
                g_scores[srow + jl0] = __float2half(s0);
                g_scores[srow + jl1] = __float2half(s1);
            }
        }
    }
}

// ---------------- K2b: sparse E path via gather + fp8 mma -------------------
#define K2S_SMEM (2*64*SME8)
__global__ void __launch_bounds__(128) k2_sparse(
    const float* __restrict__ e, const unsigned* __restrict__ adj)
{
    extern __shared__ char dyn[];
    uint8_t* es  = (uint8_t*)dyn;               // gathered rows, e4m3
    uint8_t* A1s = (uint8_t*)(dyn + 64*SME8);
    __shared__ float qs[64];
    __shared__ int lst[128];
    __shared__ int cnt;

    int bi = blockIdx.x;
    int b = bi >> 9, i = bi & 511;
    int t = threadIdx.x;
    int w = t >> 5, lane = t & 31;
    int r = lane >> 2, cq = lane & 3;
    int m0 = w * 16;

    if (t < 64) qs[t] = g_Q[bi*64 + t];
    if (t == 0) cnt = 0;
    __syncthreads();

    #pragma unroll
    for (int it = 0; it < 4; ++it) {
        int j = t + it*128;
        if (adj[(size_t)bi*512 + j]) {
            int pos = atomicAdd(&cnt, 1);
            if (pos < 128) lst[pos] = j;
        }
    }
    // A1s[hk][d] = e4m3(W_E^T[hk][d] * q[hk] * 16)
    #pragma unroll
    for (int it = 0; it < 8; ++it) {
        int idx = t + it*128;
        int hk = idx >> 4, c4 = idx & 15;
        float4 wv = ((const float4*)g_WET)[hk*16 + c4];
        float qv = qs[hk] * 16.f;
        *(uint32_t*)&A1s[hk*SME8 + c4*4] =
            packe4(wv.x*qv, wv.y*qv, wv.z*qv, wv.w*qv);
    }
    __syncthreads();
    int n = cnt;
    int ng = n < 64 ? n : 64;

    // gather adj e-rows into e4m3 tile (zero-pad beyond ng)
    #pragma unroll
    for (int it = 0; it < 8; ++it) {
        int idx = t + it*128;
        int q = idx >> 4, c4 = idx & 15;
        float4 v = make_float4(0.f, 0.f, 0.f, 0.f);
        if (q < ng) {
            int j = lst[q];
            v = *(const float4*)(e + ((size_t)bi*512 + j)*64 + c4*4);
        }
        *(uint32_t*)&es[q*SME8 + c4*4] = packe4(v.x, v.y, v.z, v.w);
    }
    __syncthreads();

    int q0 = m0 + r, q1 = q0 + 8;
    bool v0 = q0 < ng, v1 = q1 < ng;
    int j0v = v0 ? lst[q0] : 0;
    int j1v = v1 ? lst[q1] : 0;
    const float* kr0 = g_K + ((size_t)(b*512 + j0v))*64 + 2*cq;
    const float* kr1 = g_K + ((size_t)(b*512 + j1v))*64 + 2*cq;
    float2 ka[8], kb[8];
    #pragma unroll
    for (int h = 0; h < 8; ++h) {
        ka[h] = __ldg((const float2*)(kr0 + h*8));
        kb[h] = __ldg((const float2*)(kr1 + h*8));
    }

    float acc[8][4];
    #pragma unroll
    for (int nt = 0; nt < 8; ++nt)
        #pragma unroll
        for (int z = 0; z < 4; ++z) acc[nt][z] = 0.f;

    #pragma unroll
    for (int kc = 0; kc < 2; ++kc) {
        int k0 = kc*32 + cq*4;
        uint32_t a0 = *(const uint32_t*)&es[q0*SME8 + k0];
        uint32_t a1 = *(const uint32_t*)&es[q1*SME8 + k0];
        uint32_t a2 = *(const uint32_t*)&es[q0*SME8 + k0 + 16];
        uint32_t a3 = *(const uint32_t*)&es[q1*SME8 + k0 + 16];
        #pragma unroll
        for (int nt = 0; nt < 8; ++nt) {
            int nn = nt*8 + r;
            uint32_t b0 = *(const uint32_t*)&A1s[nn*SME8 + k0];
            uint32_t b1 = *(const uint32_t*)&A1s[nn*SME8 + k0 + 16];
            mma_e4m3(acc[nt], a0, a1, a2, a3, b0, b1);
        }
    }

    #pragma unroll
    for (int h = 0; h < 8; ++h) {
        float s0 = (acc[h][0]*ka[h].x + acc[h][1]*ka[h].y) * 0.0625f;
        float s1 = (acc[h][2]*kb[h].x + acc[h][3]*kb[h].y) * 0.0625f;
        s0 += __shfl_xor_sync(0xffffffffu, s0, 1);
        s0 += __shfl_xor_sync(0xffffffffu, s0, 2);
        s1 += __shfl_xor_sync(0xffffffffu, s1, 1);
        s1 += __shfl_xor_sync(0xffffffffu, s1, 2);
        if (cq == 0) {
            size_t srow = ((size_t)(b*8 + h)*BN + i)*BN;
            if (v0) g_scores[srow + j0v] = __float2half(s0);
            if (v1) g_scores[srow + j1v] = __float2half(s1);
        }
    }

    if (n > 64) {   // pathological fallback (fp32), statistically never
        int nf = n < 128 ? n : 128;
        for (int q = 64 + w; q < nf; q += 4) {
            int j = lst[q];
            const float* ep = e + ((size_t)bi*512 + j)*64;
            float y0 = 0.f, y1 = 0.f;
            for (int d = 0; d < 64; ++d) {
                float ev = ep[d];
                y0 += ev * g_WET[lane*64 + d];
                y1 += ev * g_WET[(lane+32)*64 + d];
            }
            y0 *= qs[lane];
            y1 *= qs[lane + 32];
            const float* kp = g_K + ((size_t)(b*512 + j))*64;
            float z0 = y0 * kp[lane];
            float z1 = y1 * kp[lane + 32];
            z0 += __shfl_xor_sync(0xffffffffu, z0, 1);
            z0 += __shfl_xor_sync(0xffffffffu, z0, 2);
            z0 += __shfl_xor_sync(0xffffffffu, z0, 4);
            z1 += __shfl_xor_sync(0xffffffffu, z1, 1);
            z1 += __shfl_xor_sync(0xffffffffu, z1, 2);
            z1 += __shfl_xor_sync(0xffffffffu, z1, 4);
            if ((lane & 7) == 0) {
                int h0 = lane >> 3;
                g_scores[((size_t)(b*8 + h0    )*BN + i)*BN + j] = __float2half(z0);
                g_scores[((size_t)(b*8 + h0 + 4)*BN + i)*BN + j] = __float2half(z1);
            }
        }
    }
}

// ---------------- K4: exp/mask/k_RW + rowsum + att@V (half2 loop) ------------
__global__ void __launch_bounds__(256) k4_att(
    const float* __restrict__ kRW, const float* __restrict__ mask)
{
    __shared__ float Vs[8*512];   // 16 KB
    __shared__ float msk[512];
    int bh = blockIdx.y;
    int b = bh >> 3, h = bh & 7;
    int i0 = blockIdx.x * 8;
    int t = threadIdx.x, w = t >> 5, lane = t & 31;

    const float4* vtp = (const float4*)(g_VT + ((size_t)(b*64) + h*8)*512);
    #pragma unroll
    for (int idx = t; idx < 1024; idx += 256)
        ((float4*)Vs)[idx] = vtp[idx];
    for (int j = t; j < 512; j += 256) msk[j] = mask[b*512 + j];
    __syncthreads();

    int i = i0 + w;
    float mi = msk[i];
    const __half2* sp2 = (const __half2*)(g_scores + ((size_t)(b*8 + h)*512 + i)*512);
    const float2* wp2 = (const float2*)(kRW + ((size_t)(b*512 + i))*512);
    const float2* mk2 = (const float2*)msk;

    float pden = 0.f;
    float pav[8];
    #pragma unroll
    for (int k = 0; k < 8; ++k) pav[k] = 0.f;

    #pragma unroll 4
    for (int jt = 0; jt < 8; ++jt) {
        int j2 = jt*32 + lane;               // half2 index (2 adjacent j)
        float2 sv = __half22float2(sp2[j2]);
        float2 wv = wp2[j2];
        float2 mv = mk2[j2];
        float pw0 = __expf(sv.x) * wv.x * mv.x * mi;
        float pw1 = __expf(sv.y) * wv.y * mv.y * mi;
        pden += pw0 + pw1;
        #pragma unroll
        for (int k = 0; k < 8; ++k) {
            float2 vv = *(const float2*)&Vs[k*512 + 2*j2];
            pav[k] += pw0*vv.x + pw1*vv.y;
        }
    }
    #pragma unroll
    for (int off = 16; off; off >>= 1) {
        pden += __shfl_down_sync(0xffffffffu, pden, off);
        #pragma unroll
        for (int k = 0; k < 8; ++k) pav[k] += __shfl_down_sync(0xffffffffu, pav[k], off);
    }
    if (lane == 0) {
        float inv = 1.f / fmaxf(pden, 1e-6f);
        float4* op = (float4*)&g_hatt[((size_t)(b*512 + i))*64 + h*8];
        op[0] = make_float4(pav[0]*inv, pav[1]*inv, pav[2]*inv, pav[3]*inv);
        op[1] = make_float4(pav[4]*inv, pav[5]*inv, pav[6]*inv, pav[7]*inv);
    }
}

// ---------------- K5: O-proj + LN2 + FFN + residuals. 4 rows/block ----------
__global__ void __launch_bounds__(256) k5_out(
    const float* __restrict__ hin, const float* __restrict__ OW,
    const float* __restrict__ Ob, const float* __restrict__ g2,
    const float* __restrict__ b2, const float* __restrict__ Wf1,
    const float* __restrict__ bf1, const float* __restrict__ Wf2,
    const float* __restrict__ bf2, float* __restrict__ out)
{
    int ty = threadIdx.y;
    int row = blockIdx.x*4 + ty;
    int t = threadIdx.x;
    __shared__ float has[4][64], ys[4][64], hid[4][128];
    __shared__ float red[4][4];

    has[ty][t] = g_hatt[row*64 + t];
    __syncthreads();

    float a = hin[row*64 + t] + Ob[t];
    #pragma unroll 8
    for (int d = 0; d < 64; ++d) a += has[ty][d] * OW[d*64 + t];

    float s = a, sq = a*a;
    #pragma unroll
    for (int off = 16; off; off >>= 1) {
        s  += __shfl_down_sync(0xffffffffu, s,  off);
        sq += __shfl_down_sync(0xffffffffu, sq, off);
    }
    int wid = t >> 5, lane = t & 31;
    if (lane == 0) { red[ty][wid*2] = s; red[ty][wid*2+1] = sq; }
    __syncthreads();
    float S  = red[ty][0] + red[ty][2];
    float SQ = red[ty][1] + red[ty][3];
    float mean = S * (1.f/64.f);
    float var  = SQ * (1.f/64.f) - mean*mean;
    float rinv = rsqrtf(var + 1e-5f);
    ys[ty][t] = (a - mean) * rinv * g2[t] + b2[t];
    __syncthreads();

    float h0 = bf1[t], h1 = bf1[t + 64];
    #pragma unroll 8
    for (int d = 0; d < 64; ++d) {
        float x = ys[ty][d];
        h0 += x * Wf1[d*128 + t];
        h1 += x * Wf1[d*128 + t + 64];
    }
    hid[ty][t]      = fmaxf(h0, 0.f);
    hid[ty][t + 64] = fmaxf(h1, 0.f);
    __syncthreads();

    float o = a + bf2[t];
    #pragma unroll 8
    for (int c = 0; c < 128; ++c) o += hid[ty][c] * Wf2[c*64 + t];
    out[row*64 + t] = o;
}

// ---------------- launch ----------------
extern "C" void kernel_launch(void* const* d_in, const int* in_sizes, int n_in,
                              void* d_out, int out_size)
{
    const float* h    = (const float*)d_in[0];
    const float* p    = (const float*)d_in[1];
    const float* e    = (const float*)d_in[2];
    const float* kRW  = (const float*)d_in[3];
    const float* mask = (const float*)d_in[4];
    const unsigned* adj = (const unsigned*)d_in[5];
    const float* WQ   = (const float*)d_in[6];
    const float* WK   = (const float*)d_in[7];
    const float* WV   = (const float*)d_in[8];
    const float* WQ2  = (const float*)d_in[9];
    const float* WK2  = (const float*)d_in[10];
    const float* WE   = (const float*)d_in[11];
    const float* WE2  = (const float*)d_in[12];
    const float* OW   = (const float*)d_in[13];
    const float* Ob   = (const float*)d_in[14];
    const float* g1   = (const float*)d_in[15];
    const float* b1   = (const float*)d_in[16];
    const float* g2   = (const float*)d_in[17];
    const float* b2   = (const float*)d_in[18];
    const float* Wf1  = (const float*)d_in[19];
    const float* bf1  = (const float*)d_in[20];
    const float* Wf2  = (const float*)d_in[21];
    const float* bf2  = (const float*)d_in[22];
    float* out = (float*)d_out;

    k0_init<<<1, 256>>>(WE, WE2);
    k1_proj<<<512, dim3(64,4)>>>(h, p, g1, b1, WQ, WK, WV, WQ2, WK2);
    k2_dense<<<NROWS, 128, K2_SMEM>>>(e);
    k2_sparse<<<NROWS, 128, K2S_SMEM>>>(e, adj);
    k4_att<<<dim3(64, 32), 256>>>(kRW, mask);
    k5_out<<<512, dim3(64,4)>>>(h, OW, Ob, g2, b2, Wf1, bf1, Wf2, bf2, out);
}